// round 4
// baseline (speedup 1.0000x reference)
#include <cuda_runtime.h>

#define NN 100000
#define NE 3200000
#define FIN 25
#define FH  16
#define FO  2

// ---- scratch (device globals; no allocation anywhere) ----
__device__ int   g_cnt[NN];
__device__ int   g_off[NN + 1];
__device__ int   g_pos[NN];
__device__ int   g_src[NE];
__device__ float g_dinv[NN];
__device__ __align__(16) float g_hs1[NN * FH];  // (x@W1) * dinv[src]
__device__ __align__(16) float g_hs2[NN * FO];  // (h1@W2) * dinv[src]

// ---------------------------------------------------------------------------
__global__ void k_zero_cnt() {
    int i = blockIdx.x * blockDim.x + threadIdx.x;
    if (i < NN) g_cnt[i] = 0;
}

// in-degree count (excluding self loop; +1 added in scan)
__global__ void k_count(const int* __restrict__ ei) {
    int e = blockIdx.x * blockDim.x + threadIdx.x;
    if (e < NE) {
        int c = ei[NE + e];   // target
        atomicAdd(&g_cnt[c], 1);
    }
}

// single-block exclusive scan of g_cnt -> g_off (and g_pos copy), plus dinv
__global__ void k_scan() {
    const int T = 1024;
    const int CH = (NN + T - 1) / T;  // 98
    __shared__ int ssum[T];
    int t = threadIdx.x;
    int beg = t * CH;
    int end = min(beg + CH, NN);
    int s = 0;
    for (int i = beg; i < end; i++) s += g_cnt[i];
    ssum[t] = s;
    __syncthreads();
    // inclusive Hillis-Steele block scan
    for (int d = 1; d < T; d <<= 1) {
        int v = (t >= d) ? ssum[t - d] : 0;
        __syncthreads();
        ssum[t] += v;
        __syncthreads();
    }
    int run = (t == 0) ? 0 : ssum[t - 1];
    for (int i = beg; i < end; i++) {
        int c = g_cnt[i];
        g_off[i] = run;
        g_pos[i] = run;
        g_dinv[i] = rsqrtf((float)(c + 1));  // +1 self loop; always > 0
        run += c;
    }
    if (t == T - 1) g_off[NN] = run;
}

// place sources into CSR buckets keyed by target
__global__ void k_fill(const int* __restrict__ ei) {
    int e = blockIdx.x * blockDim.x + threadIdx.x;
    if (e < NE) {
        int r = ei[e];        // source
        int c = ei[NE + e];   // target
        int p = atomicAdd(&g_pos[c], 1);
        g_src[p] = r;
    }
}

// hs1[n] = (x[n] @ W1) * dinv[n]
__global__ void k_xw1(const float* __restrict__ x, const float* __restrict__ W1) {
    __shared__ float sW[FIN * FH];
    int tid = threadIdx.x;
    for (int i = tid; i < FIN * FH; i += blockDim.x) sW[i] = W1[i];
    __syncthreads();
    int n = blockIdx.x * blockDim.x + tid;
    if (n >= NN) return;
    float xi[FIN];
#pragma unroll
    for (int k = 0; k < FIN; k++) xi[k] = x[n * FIN + k];
    float d = g_dinv[n];
    float o[FH];
#pragma unroll
    for (int f = 0; f < FH; f++) {
        float acc = 0.f;
#pragma unroll
        for (int k = 0; k < FIN; k++) acc += xi[k] * sW[k * FH + f];
        o[f] = acc * d;
    }
    float4* dst = (float4*)&g_hs1[n * FH];
    dst[0] = make_float4(o[0], o[1], o[2], o[3]);
    dst[1] = make_float4(o[4], o[5], o[6], o[7]);
    dst[2] = make_float4(o[8], o[9], o[10], o[11]);
    dst[3] = make_float4(o[12], o[13], o[14], o[15]);
}

// gather layer-1 messages, finalize (+b1, ReLU), apply W2, pre-scale by dinv
__global__ void k_layer1(const float* __restrict__ b1, const float* __restrict__ W2) {
    __shared__ float sW2[FH * FO];
    __shared__ float sb1[FH];
    int tid = threadIdx.x;
    if (tid < FH * FO) sW2[tid] = W2[tid];
    if (tid < FH) sb1[tid] = b1[tid];
    __syncthreads();
    int n = blockIdx.x * blockDim.x + tid;
    if (n >= NN) return;

    float acc[FH];
    {   // self-loop contribution: hs1[n]
        const float4* p = (const float4*)&g_hs1[n * FH];
        float4 v0 = p[0], v1 = p[1], v2 = p[2], v3 = p[3];
        acc[0] = v0.x; acc[1] = v0.y; acc[2] = v0.z; acc[3] = v0.w;
        acc[4] = v1.x; acc[5] = v1.y; acc[6] = v1.z; acc[7] = v1.w;
        acc[8] = v2.x; acc[9] = v2.y; acc[10] = v2.z; acc[11] = v2.w;
        acc[12] = v3.x; acc[13] = v3.y; acc[14] = v3.z; acc[15] = v3.w;
    }
    int beg = g_off[n], end = g_off[n + 1];
    for (int k = beg; k < end; k++) {
        int j = g_src[k];
        const float4* p = (const float4*)&g_hs1[j * FH];
        float4 v0 = p[0], v1 = p[1], v2 = p[2], v3 = p[3];
        acc[0] += v0.x; acc[1] += v0.y; acc[2] += v0.z; acc[3] += v0.w;
        acc[4] += v1.x; acc[5] += v1.y; acc[6] += v1.z; acc[7] += v1.w;
        acc[8] += v2.x; acc[9] += v2.y; acc[10] += v2.z; acc[11] += v2.w;
        acc[12] += v3.x; acc[13] += v3.y; acc[14] += v3.z; acc[15] += v3.w;
    }
    float d = g_dinv[n];
    float z0 = 0.f, z1 = 0.f;
#pragma unroll
    for (int f = 0; f < FH; f++) {
        float h = fmaxf(d * acc[f] + sb1[f], 0.f);
        z0 += h * sW2[f * FO + 0];
        z1 += h * sW2[f * FO + 1];
    }
    float2* dst = (float2*)&g_hs2[n * FO];
    *dst = make_float2(z0 * d, z1 * d);
}

// gather layer-2 messages, finalize (+b2), log-softmax over 2 classes
__global__ void k_layer2(const float* __restrict__ b2, float* __restrict__ out) {
    int n = blockIdx.x * blockDim.x + threadIdx.x;
    if (n >= NN) return;
    float2 self = *(const float2*)&g_hs2[n * FO];
    float a0 = self.x, a1 = self.y;
    int beg = g_off[n], end = g_off[n + 1];
    for (int k = beg; k < end; k++) {
        int j = g_src[k];
        float2 v = *(const float2*)&g_hs2[j * FO];
        a0 += v.x; a1 += v.y;
    }
    float d = g_dinv[n];
    float z0 = d * a0 + b2[0];
    float z1 = d * a1 + b2[1];
    float m = fmaxf(z0, z1);
    float lse = m + logf(expf(z0 - m) + expf(z1 - m));
    out[n * FO + 0] = z0 - lse;
    out[n * FO + 1] = z1 - lse;
}

// ---------------------------------------------------------------------------
extern "C" void kernel_launch(void* const* d_in, const int* in_sizes, int n_in,
                              void* d_out, int out_size) {
    const float* x  = (const float*)d_in[0];
    const int*   ei = (const int*)d_in[1];   // JAX default: int64 request -> int32 array
    const float* W1 = (const float*)d_in[2];
    const float* b1 = (const float*)d_in[3];
    const float* W2 = (const float*)d_in[4];
    const float* b2 = (const float*)d_in[5];
    float* out = (float*)d_out;

    const int TB = 256;
    k_zero_cnt<<<(NN + TB - 1) / TB, TB>>>();
    k_count<<<(NE + TB - 1) / TB, TB>>>(ei);
    k_scan<<<1, 1024>>>();
    k_fill<<<(NE + TB - 1) / TB, TB>>>(ei);
    k_xw1<<<(NN + 127) / 128, 128>>>(x, W1);
    k_layer1<<<(NN + 127) / 128, 128>>>(b1, W2);
    k_layer2<<<(NN + 127) / 128, 128>>>(b2, out);
}

// round 5
// speedup vs baseline: 2.8308x; 2.8308x over previous
#include <cuda_runtime.h>

#define NN 100000
#define NE 3200000
#define FIN 25
#define FH  16
#define FO  2
#define NBLK ((NN + 255) / 256)   // 391 scan blocks

// ---- scratch (device globals; no allocation anywhere) ----
__device__ int   g_cnt[NN];
__device__ int   g_off[NN + 1];
__device__ int   g_slot[NE];
__device__ int   g_src[NE];
__device__ int   g_bsum[NBLK];
__device__ int   g_boff[NBLK];
__device__ float g_dinv[NN];
__device__ __align__(16) float g_hs1[NN * FH];  // (x@W1) * dinv[src]
__device__ __align__(16) float g_hs2[NN * FO];  // (h1@W2) * dinv[src]

// ---------------------------------------------------------------------------
__global__ void k_zero_cnt() {
    int i = blockIdx.x * blockDim.x + threadIdx.x;
    if (i < NN) g_cnt[i] = 0;
}

// pass 1: in-degree count + per-edge slot record (2 edges per thread)
__global__ void k_count_slot(const int* __restrict__ ei) {
    int e = (blockIdx.x * blockDim.x + threadIdx.x) * 2;
    if (e < NE) {
        int2 c2 = *(const int2*)&ei[NE + e];
        g_slot[e]     = atomicAdd(&g_cnt[c2.x], 1);
        g_slot[e + 1] = atomicAdd(&g_cnt[c2.y], 1);
    }
}

// scan phase A: per-block sums of g_cnt
__global__ void k_scan_partial() {
    __shared__ int s[256];
    int t = threadIdx.x;
    int i = blockIdx.x * 256 + t;
    int c = (i < NN) ? g_cnt[i] : 0;
    s[t] = c;
    __syncthreads();
    for (int d = 128; d > 0; d >>= 1) {
        if (t < d) s[t] += s[t + d];
        __syncthreads();
    }
    if (t == 0) g_bsum[blockIdx.x] = s[0];
}

// scan phase B: single block scans the 391 block sums
__global__ void k_scan_sums() {
    __shared__ int s[512];
    int t = threadIdx.x;
    int v = (t < NBLK) ? g_bsum[t] : 0;
    s[t] = v;
    __syncthreads();
    for (int d = 1; d < 512; d <<= 1) {
        int u = (t >= d) ? s[t - d] : 0;
        __syncthreads();
        s[t] += u;
        __syncthreads();
    }
    if (t < NBLK) g_boff[t] = s[t] - v;         // exclusive
    if (t == NBLK - 1) g_off[NN] = s[t];        // total
}

// scan phase C: block-local exclusive scan + block offset; also dinv
__global__ void k_scan_apply() {
    __shared__ int s[256];
    int t = threadIdx.x;
    int i = blockIdx.x * 256 + t;
    int c = (i < NN) ? g_cnt[i] : 0;
    s[t] = c;
    __syncthreads();
    for (int d = 1; d < 256; d <<= 1) {
        int u = (t >= d) ? s[t - d] : 0;
        __syncthreads();
        s[t] += u;
        __syncthreads();
    }
    if (i < NN) {
        g_off[i]  = s[t] - c + g_boff[blockIdx.x];
        g_dinv[i] = rsqrtf((float)(c + 1));     // +1 self loop
    }
}

// pass 2: atomic-free CSR scatter (2 edges per thread)
__global__ void k_scatter(const int* __restrict__ ei) {
    int e = (blockIdx.x * blockDim.x + threadIdx.x) * 2;
    if (e < NE) {
        int2 r2 = *(const int2*)&ei[e];
        int2 c2 = *(const int2*)&ei[NE + e];
        int2 s2 = *(const int2*)&g_slot[e];
        g_src[g_off[c2.x] + s2.x] = r2.x;
        g_src[g_off[c2.y] + s2.y] = r2.y;
    }
}

// hs1[n] = (x[n] @ W1) * dinv[n] — smem-staged x tile for coalesced loads
__global__ void k_xw1(const float* __restrict__ x, const float* __restrict__ W1) {
    __shared__ float sW[FIN * FH];
    __shared__ float sx[128 * FIN];
    int tid = threadIdx.x;
    for (int i = tid; i < FIN * FH; i += blockDim.x) sW[i] = W1[i];
    int base = blockIdx.x * 128;
    int lim = min(128, NN - base) * FIN;
    for (int i = tid; i < lim; i += blockDim.x) sx[i] = x[base * FIN + i];
    __syncthreads();
    int n = base + tid;
    if (n >= NN) return;
    float xi[FIN];
#pragma unroll
    for (int k = 0; k < FIN; k++) xi[k] = sx[tid * FIN + k];
    float d = g_dinv[n];
    float o[FH];
#pragma unroll
    for (int f = 0; f < FH; f++) {
        float acc = 0.f;
#pragma unroll
        for (int k = 0; k < FIN; k++) acc += xi[k] * sW[k * FH + f];
        o[f] = acc * d;
    }
    float4* dst = (float4*)&g_hs1[n * FH];
    dst[0] = make_float4(o[0], o[1], o[2], o[3]);
    dst[1] = make_float4(o[4], o[5], o[6], o[7]);
    dst[2] = make_float4(o[8], o[9], o[10], o[11]);
    dst[3] = make_float4(o[12], o[13], o[14], o[15]);
}

// layer-1 gather: warp per node; lane = (edge group 0..7, 16B chunk 0..3)
__global__ void k_layer1(const float* __restrict__ b1, const float* __restrict__ W2) {
    __shared__ float sW2[FH * FO];
    __shared__ float sb1[FH];
    int tid = threadIdx.x;
    if (tid < FH * FO) sW2[tid] = W2[tid];
    if (tid < FH) sb1[tid] = b1[tid];
    __syncthreads();
    int n = (blockIdx.x * blockDim.x + tid) >> 5;
    if (n >= NN) return;
    int lane = tid & 31;
    int sub  = lane & 3;       // which float4 chunk of the 16-feature row
    int grp  = lane >> 2;      // which edge slot (8 concurrent edges)

    int beg = g_off[n], end = g_off[n + 1];
    float4 a = make_float4(0.f, 0.f, 0.f, 0.f);
    for (int k = beg + grp; k < end; k += 8) {
        int j = g_src[k];
        float4 v = ((const float4*)g_hs1)[j * 4 + sub];
        a.x += v.x; a.y += v.y; a.z += v.z; a.w += v.w;
    }
    // reduce across edge groups (lanes sharing `sub`)
#pragma unroll
    for (int off = 4; off < 32; off <<= 1) {
        a.x += __shfl_xor_sync(0xffffffffu, a.x, off);
        a.y += __shfl_xor_sync(0xffffffffu, a.y, off);
        a.z += __shfl_xor_sync(0xffffffffu, a.z, off);
        a.w += __shfl_xor_sync(0xffffffffu, a.w, off);
    }
    // self-loop contribution
    float4 s = ((const float4*)g_hs1)[n * 4 + sub];
    a.x += s.x; a.y += s.y; a.z += s.z; a.w += s.w;

    float d = g_dinv[n];
    int f0 = sub * 4;
    float h0 = fmaxf(d * a.x + sb1[f0 + 0], 0.f);
    float h1 = fmaxf(d * a.y + sb1[f0 + 1], 0.f);
    float h2 = fmaxf(d * a.z + sb1[f0 + 2], 0.f);
    float h3 = fmaxf(d * a.w + sb1[f0 + 3], 0.f);
    float z0 = h0 * sW2[(f0 + 0) * FO] + h1 * sW2[(f0 + 1) * FO]
             + h2 * sW2[(f0 + 2) * FO] + h3 * sW2[(f0 + 3) * FO];
    float z1 = h0 * sW2[(f0 + 0) * FO + 1] + h1 * sW2[(f0 + 1) * FO + 1]
             + h2 * sW2[(f0 + 2) * FO + 1] + h3 * sW2[(f0 + 3) * FO + 1];
    // reduce across the 4 sub chunks
    z0 += __shfl_xor_sync(0xffffffffu, z0, 1);
    z0 += __shfl_xor_sync(0xffffffffu, z0, 2);
    z1 += __shfl_xor_sync(0xffffffffu, z1, 1);
    z1 += __shfl_xor_sync(0xffffffffu, z1, 2);
    if (lane == 0)
        ((float2*)g_hs2)[n] = make_float2(z0 * d, z1 * d);
}

// layer-2 gather: warp per node; lane per edge
__global__ void k_layer2(const float* __restrict__ b2, float* __restrict__ out) {
    int tid = threadIdx.x;
    int n = (blockIdx.x * blockDim.x + tid) >> 5;
    if (n >= NN) return;
    int lane = tid & 31;
    int beg = g_off[n], end = g_off[n + 1];
    float a0 = 0.f, a1 = 0.f;
    for (int k = beg + lane; k < end; k += 32) {
        float2 v = ((const float2*)g_hs2)[g_src[k]];
        a0 += v.x; a1 += v.y;
    }
#pragma unroll
    for (int off = 1; off < 32; off <<= 1) {
        a0 += __shfl_xor_sync(0xffffffffu, a0, off);
        a1 += __shfl_xor_sync(0xffffffffu, a1, off);
    }
    if (lane == 0) {
        float2 s = ((const float2*)g_hs2)[n];
        float d = g_dinv[n];
        float z0 = d * (a0 + s.x) + b2[0];
        float z1 = d * (a1 + s.y) + b2[1];
        float m = fmaxf(z0, z1);
        float lse = m + logf(expf(z0 - m) + expf(z1 - m));
        ((float2*)out)[n] = make_float2(z0 - lse, z1 - lse);
    }
}

// ---------------------------------------------------------------------------
extern "C" void kernel_launch(void* const* d_in, const int* in_sizes, int n_in,
                              void* d_out, int out_size) {
    const float* x  = (const float*)d_in[0];
    const int*   ei = (const int*)d_in[1];   // int32 (JAX x64 disabled)
    const float* W1 = (const float*)d_in[2];
    const float* b1 = (const float*)d_in[3];
    const float* W2 = (const float*)d_in[4];
    const float* b2 = (const float*)d_in[5];
    float* out = (float*)d_out;

    const int TB = 256;
    k_zero_cnt<<<(NN + TB - 1) / TB, TB>>>();
    k_count_slot<<<(NE / 2 + TB - 1) / TB, TB>>>(ei);
    k_scan_partial<<<NBLK, 256>>>();
    k_scan_sums<<<1, 512>>>();
    k_scan_apply<<<NBLK, 256>>>();
    k_scatter<<<(NE / 2 + TB - 1) / TB, TB>>>(ei);
    k_xw1<<<(NN + 127) / 128, 128>>>(x, W1);
    k_layer1<<<(NN * 32 + TB - 1) / TB, TB>>>(b1, W2);
    k_layer2<<<(NN * 32 + TB - 1) / TB, TB>>>(b2, out);
}